// round 1
// baseline (speedup 1.0000x reference)
// SampleScoreModel: softmax-weighted Gaussian-kernel score.
//   out[b] = (1/sigma_b) * ( softmax_n( -||s_n - x_b||^2 / (2 sigma_b^2) ) @ samples - x_b )
// Flash-attention-style fused kernel: one pass over the 16MB sample bank,
// all 32 batches share each tile. Online softmax (m, l, acc) partials per CTA,
// combined by a small reduce kernel.
#include <cuda_runtime.h>
#include <math.h>
#include <float.h>

#define B 32
#define D 64
#define NS 65536
#define TILE 128
#define NTILES_TOTAL (NS / TILE)                 // 512
#define GRID_MAIN 256
#define TILES_PER_CTA (NTILES_TOTAL / GRID_MAIN) // 2
#define THREADS 256

#define ST_STRIDE 132
#define XS_STRIDE 34
#define G_STRIDE 132

// bank swizzle on the n index (bits2..4 ^= bits3..5): bijective on 0..127,
// preserves 4-word granules -> LDS.128 stays legal; spreads 8-strided and
// 16-strided row accesses across 8 bank-groups.
#define SW(n) ((n) ^ ((((n) >> 3) & 7) << 2))

// smem layout (floats)
#define OFF_ST 0                                  // 64*132 = 8448
#define OFF_G  (64 * ST_STRIDE)                   // 32*132 = 4224
#define OFF_XS (OFF_G + 32 * G_STRIDE)            // 64*34  = 2176
#define OFF_CB (OFF_XS + 64 * XS_STRIDE)
#define OFF_M  (OFF_CB + 32)
#define OFF_L  (OFF_M + 32)
#define OFF_AL (OFF_L + 32)
#define SMEM_FLOATS (OFF_AL + 32)
#define SMEM_BYTES (SMEM_FLOATS * 4)              // 59904 B

__device__ float g_acc[GRID_MAIN][B][D];
__device__ float g_m[GRID_MAIN][B];
__device__ float g_l[GRID_MAIN][B];

__global__ __launch_bounds__(THREADS, 2)
void score_partial_kernel(const float* __restrict__ t,
                          const float* __restrict__ x,
                          const float* __restrict__ samples) {
    extern __shared__ float sm[];
    float* st   = sm + OFF_ST;   // sample tile, transposed [d][n], swizzled
    float* G    = sm + OFF_G;    // logits / weights tile [b][n]
    float* xs   = sm + OFF_XS;   // x transposed [d][b]
    float* cb_s = sm + OFF_CB;   // 0.5 / sigma^2 per b
    float* m_s  = sm + OFF_M;    // running max per b
    float* l_s  = sm + OFF_L;    // running sumexp per b
    float* al_s = sm + OFF_AL;   // per-tile rescale alpha per b

    const int tid = threadIdx.x;

    // ---- setup: x transpose + per-b constants ----
#pragma unroll
    for (int i = tid; i < B * D; i += THREADS) {
        int b = i / D, k = i % D;
        xs[k * XS_STRIDE + b] = x[i];
    }
    if (tid < B) {
        float sig = 0.01f * expf(t[tid] * 9.210340371976184f); // sigma_min*(smax/smin)^t
        cb_s[tid] = 0.5f / (sig * sig);
        m_s[tid] = -FLT_MAX;
        l_s[tid] = 0.0f;
    }
    __syncthreads();

    // ---- thread mappings ----
    const int lane = tid & 31;
    const int w    = tid >> 5;
    const int d4h  = lane >> 4;     // 0..1
    const int nn   = lane & 15;     // 0..15
    const int d4   = 2 * w + d4h;   // 0..15 (float4 column of samples)

    const int bg = tid >> 4;        // 0..15
    const int b0 = bg << 1;
    const int ng = tid & 15;        // 0..15
    const int n0 = ng << 3;
    const int pn0 = SW(n0);
    const int pn1 = SW(n0 + 4);

    const int row = tid >> 3;       // finalize: b row, 8 threads per row
    const int sub = tid & 7;

    const int dq = tid & 15;        // acc gemm: d group

    float acc[2][4];
#pragma unroll
    for (int a = 0; a < 2; a++)
#pragma unroll
        for (int j = 0; j < 4; j++) acc[a][j] = 0.0f;

    const float4* sp = (const float4*)samples;
    float4 v[8];
    {   // preload tile 0
        int tileN = blockIdx.x * (TILES_PER_CTA * TILE);
#pragma unroll
        for (int i = 0; i < 8; i++)
            v[i] = sp[(size_t)(tileN + 16 * i + nn) * 16 + d4];
    }

    for (int tt = 0; tt < TILES_PER_CTA; ++tt) {
        // ---- transpose-store tile into smem (conflict-free via lane map + SW) ----
#pragma unroll
        for (int i = 0; i < 8; i++) {
            int pn = SW(16 * i + nn);
            float* p = &st[(4 * d4) * ST_STRIDE + pn];
            p[0 * ST_STRIDE] = v[i].x;
            p[1 * ST_STRIDE] = v[i].y;
            p[2 * ST_STRIDE] = v[i].z;
            p[3 * ST_STRIDE] = v[i].w;
        }
        __syncthreads();

        // prefetch next tile into regs (latency hidden behind this tile's compute)
        if (tt + 1 < TILES_PER_CTA) {
            int tileN = blockIdx.x * (TILES_PER_CTA * TILE) + (tt + 1) * TILE;
#pragma unroll
            for (int i = 0; i < 8; i++)
                v[i] = sp[(size_t)(tileN + 16 * i + nn) * 16 + d4];
        }

        // ---- squared-distance GEMM: dist[b][n] = sum_k (s[n][k] - x[b][k])^2 ----
        float dist[2][8];
#pragma unroll
        for (int a = 0; a < 2; a++)
#pragma unroll
            for (int j = 0; j < 8; j++) dist[a][j] = 0.0f;

#pragma unroll 8
        for (int k = 0; k < D; ++k) {
            const float2 xv = *(const float2*)&xs[k * XS_STRIDE + b0];
            const float4 s0 = *(const float4*)&st[k * ST_STRIDE + pn0];
            const float4 s1 = *(const float4*)&st[k * ST_STRIDE + pn1];
            float sv[8] = {s0.x, s0.y, s0.z, s0.w, s1.x, s1.y, s1.z, s1.w};
#pragma unroll
            for (int j = 0; j < 8; j++) {
                float da = sv[j] - xv.x; dist[0][j] = fmaf(da, da, dist[0][j]);
                float db = sv[j] - xv.y; dist[1][j] = fmaf(db, db, dist[1][j]);
            }
        }
        *(float4*)&G[(b0    ) * G_STRIDE + n0    ] = make_float4(dist[0][0], dist[0][1], dist[0][2], dist[0][3]);
        *(float4*)&G[(b0    ) * G_STRIDE + n0 + 4] = make_float4(dist[0][4], dist[0][5], dist[0][6], dist[0][7]);
        *(float4*)&G[(b0 + 1) * G_STRIDE + n0    ] = make_float4(dist[1][0], dist[1][1], dist[1][2], dist[1][3]);
        *(float4*)&G[(b0 + 1) * G_STRIDE + n0 + 4] = make_float4(dist[1][4], dist[1][5], dist[1][6], dist[1][7]);
        __syncthreads();

        // ---- finalize: logits, online-softmax merge, weights ----
        {
            const float c = cb_s[row];
            float* gp = &G[row * G_STRIDE + sub * 16];
            float gv[16];
#pragma unroll
            for (int q = 0; q < 4; q++) {
                float4 dv = *(const float4*)&gp[4 * q];
                gv[4 * q + 0] = -dv.x * c;
                gv[4 * q + 1] = -dv.y * c;
                gv[4 * q + 2] = -dv.z * c;
                gv[4 * q + 3] = -dv.w * c;
            }
            float mt = gv[0];
#pragma unroll
            for (int i = 1; i < 16; i++) mt = fmaxf(mt, gv[i]);
            mt = fmaxf(mt, __shfl_xor_sync(0xffffffffu, mt, 1));
            mt = fmaxf(mt, __shfl_xor_sync(0xffffffffu, mt, 2));
            mt = fmaxf(mt, __shfl_xor_sync(0xffffffffu, mt, 4));
            float m_old = m_s[row];              // same-warp read-before-write
            float m_new = fmaxf(m_old, mt);
            if (sub == 0) {
                float a = __expf(m_old - m_new); // first tile: exp(-huge) = 0
                m_s[row]  = m_new;
                al_s[row] = a;
                l_s[row] *= a;
            }
            float lsum = 0.0f;
#pragma unroll
            for (int i = 0; i < 16; i++) {
                float p = __expf(gv[i] - m_new);
                gv[i] = p;
                lsum += p;
            }
#pragma unroll
            for (int q = 0; q < 4; q++)
                *(float4*)&gp[4 * q] = make_float4(gv[4 * q], gv[4 * q + 1], gv[4 * q + 2], gv[4 * q + 3]);
            lsum += __shfl_xor_sync(0xffffffffu, lsum, 1);
            lsum += __shfl_xor_sync(0xffffffffu, lsum, 2);
            lsum += __shfl_xor_sync(0xffffffffu, lsum, 4);
            if (sub == 0) l_s[row] += lsum;
        }
        __syncthreads();

        // ---- acc GEMM: acc[b][d] = alpha*acc + sum_n p[b][n] * s[n][d] ----
        {
            const float a0 = al_s[b0], a1 = al_s[b0 + 1];
#pragma unroll
            for (int j = 0; j < 4; j++) { acc[0][j] *= a0; acc[1][j] *= a1; }
            const float* Gr0 = &G[b0 * G_STRIDE];
            const float* Gr1 = &G[(b0 + 1) * G_STRIDE];
#pragma unroll 4
            for (int nq = 0; nq < TILE; nq += 4) {
                const int pn = SW(nq);
                const float4 p0 = *(const float4*)&Gr0[nq];
                const float4 p1 = *(const float4*)&Gr1[nq];
#pragma unroll
                for (int j = 0; j < 4; j++) {
                    const float4 svv = *(const float4*)&st[(dq + 16 * j) * ST_STRIDE + pn];
                    acc[0][j] = fmaf(p0.x, svv.x, acc[0][j]);
                    acc[0][j] = fmaf(p0.y, svv.y, acc[0][j]);
                    acc[0][j] = fmaf(p0.z, svv.z, acc[0][j]);
                    acc[0][j] = fmaf(p0.w, svv.w, acc[0][j]);
                    acc[1][j] = fmaf(p1.x, svv.x, acc[1][j]);
                    acc[1][j] = fmaf(p1.y, svv.y, acc[1][j]);
                    acc[1][j] = fmaf(p1.z, svv.z, acc[1][j]);
                    acc[1][j] = fmaf(p1.w, svv.w, acc[1][j]);
                }
            }
        }
        __syncthreads();  // protect st before next tile's transpose-store
    }

    // ---- write partials ----
#pragma unroll
    for (int j = 0; j < 4; j++) {
        g_acc[blockIdx.x][b0    ][dq + 16 * j] = acc[0][j];
        g_acc[blockIdx.x][b0 + 1][dq + 16 * j] = acc[1][j];
    }
    if (tid < B) {
        g_m[blockIdx.x][tid] = m_s[tid];
        g_l[blockIdx.x][tid] = l_s[tid];
    }
}

__global__ __launch_bounds__(512)
void score_reduce_kernel(const float* __restrict__ t,
                         const float* __restrict__ x,
                         float* __restrict__ out) {
    const int b = blockIdx.x;
    const int tid = threadIdx.x;
    __shared__ float sM;
    __shared__ float racc[8][D + 1];
    __shared__ float rl[8];

    if (tid < 32) {
        float m = -FLT_MAX;
        for (int i = tid; i < GRID_MAIN; i += 32) m = fmaxf(m, g_m[i][b]);
#pragma unroll
        for (int s = 16; s; s >>= 1) m = fmaxf(m, __shfl_xor_sync(0xffffffffu, m, s));
        if (tid == 0) sM = m;
    }
    __syncthreads();
    const float M = sM;
    const int ig = tid >> 6;   // 0..7
    const int d  = tid & 63;
    float accd = 0.0f, accl = 0.0f;
#pragma unroll 8
    for (int i = ig; i < GRID_MAIN; i += 8) {
        float e = __expf(g_m[i][b] - M);
        accd = fmaf(e, g_acc[i][b][d], accd);
        accl = fmaf(e, g_l[i][b], accl);
    }
    racc[ig][d] = accd;
    if (d == 0) rl[ig] = accl;
    __syncthreads();
    if (tid < D) {
        float A = 0.0f, L = 0.0f;
#pragma unroll
        for (int g2 = 0; g2 < 8; g2++) { A += racc[g2][tid]; L += rl[g2]; }
        float sig = 0.01f * expf(t[b] * 9.210340371976184f);
        // t_scale/denom = sig/sig^2 = 1/sig  (MODEL_SIGMA_MIN = 0)
        out[b * D + tid] = (1.0f / sig) * (A / L - x[b * D + tid]);
    }
}

extern "C" void kernel_launch(void* const* d_in, const int* in_sizes, int n_in,
                              void* d_out, int out_size) {
    const float* t = nullptr;
    const float* x = nullptr;
    const float* s = nullptr;
    for (int i = 0; i < n_in; i++) {
        if      (in_sizes[i] == B)          t = (const float*)d_in[i];
        else if (in_sizes[i] == B * D)      x = (const float*)d_in[i];
        else if (in_sizes[i] == NS * D)     s = (const float*)d_in[i];
    }
    cudaFuncSetAttribute(score_partial_kernel,
                         cudaFuncAttributeMaxDynamicSharedMemorySize, SMEM_BYTES);
    score_partial_kernel<<<GRID_MAIN, THREADS, SMEM_BYTES>>>(t, x, s);
    score_reduce_kernel<<<B, 512>>>(t, x, (float*)d_out);
}

// round 2
// speedup vs baseline: 1.3412x; 1.3412x over previous
// SampleScoreModel: softmax-weighted Gaussian-kernel score (flash-attention style).
//   out[b] = (1/sigma_b) * ( softmax_n( -||s_n - x_b||^2 / (2 sigma_b^2) ) @ samples - x_b )
// One 256-sample tile per CTA (no online softmax); partials (m,l,acc) reduced
// by a second small kernel. Distance via q_n - 2<s,x> (r_b dropped: row-constant
// cancels in softmax). Sample tile stored [d][n] with a d-dependent XOR column
// swizzle so both GEMMs read conflict-free.
#include <cuda_runtime.h>
#include <math.h>
#include <float.h>

#define B 32
#define D 64
#define NS 65536
#define TILE 256
#define GRID_MAIN (NS / TILE)   // 256
#define THREADS 256

#define ST_STRIDE 256
#define G_STRIDE 256
#define XS_STRIDE 36

// base column swizzle (bits2..4 ^= bits3..5); bijective per 32-block, keeps 4-float granules
#define SW(n) ((n) ^ ((((n) >> 3) & 7) << 2))

// smem layout (floats)
#define OFF_ST 0                         // 64*256 = 16384
#define OFF_G  16384                     // 32*256 = 8192
#define OFF_XS 24576                     // 64*36  = 2304
#define OFF_Q  26880                     // 256
#define OFF_CB 27136                     // 32
#define OFF_M  27168                     // 32
#define OFF_L  27200                     // 32
#define SMEM_FLOATS 27232
#define SMEM_BYTES (SMEM_FLOATS * 4)     // 108,928 B -> 2 CTAs/SM

__device__ float g_acc[GRID_MAIN][B][D];
__device__ float g_m[GRID_MAIN][B];
__device__ float g_l[GRID_MAIN][B];

__global__ __launch_bounds__(THREADS, 2)
void score_partial_kernel(const float* __restrict__ t,
                          const float* __restrict__ x,
                          const float* __restrict__ samples) {
    extern __shared__ float sm[];
    float* st   = sm + OFF_ST;   // sample tile [d][pcol], pcol = SW(n) ^ (((d>>3)&7)<<2)
    float* G    = sm + OFF_G;    // dot products -> weights, [b][SW(n)]
    float* xs   = sm + OFF_XS;   // x transposed [k][b]
    float* qn_s = sm + OFF_Q;    // ||s_n||^2 per n
    float* cb_s = sm + OFF_CB;   // 0.5 / sigma^2 per b
    float* m_s  = sm + OFF_M;
    float* l_s  = sm + OFF_L;

    const int tid = threadIdx.x;

    // ---- setup: x transpose + per-b constants ----
#pragma unroll
    for (int i = tid; i < B * D; i += THREADS) {
        int b = i >> 6, k = i & 63;
        xs[k * XS_STRIDE + b] = x[i];
    }
    if (tid < B) {
        float sig = 0.01f * expf(t[tid] * 9.210340371976184f); // smin*(smax/smin)^t
        cb_s[tid] = 0.5f / (sig * sig);
    }

    // ---- coalesced global load: flat float4 index = tid + 256*j ----
    const int nn2 = tid >> 4;     // row within 16-group
    const int d4  = tid & 15;     // float4 column
    const float4* sp = (const float4*)samples;
    const size_t base = (size_t)blockIdx.x * (TILE * (D / 4));
    float4 v[16];
#pragma unroll
    for (int j = 0; j < 16; j++) v[j] = sp[base + tid + 256 * j];

    // ---- transpose-store into st with d-dependent swizzle ----
    const int h4st = (d4 >> 1) << 2;      // ((d>>3)&7)<<2 for rows 4*d4..4*d4+3
#pragma unroll
    for (int j = 0; j < 16; j++) {
        int n = 16 * j + nn2;
        int pc = SW(n) ^ h4st;
        float* p = &st[(4 * d4) * ST_STRIDE + pc];
        p[0 * ST_STRIDE] = v[j].x;
        p[1 * ST_STRIDE] = v[j].y;
        p[2 * ST_STRIDE] = v[j].z;
        p[3 * ST_STRIDE] = v[j].w;
    }
    __syncthreads();

    // ---- q_n = ||s_n||^2 (column pass, one n per thread) ----
    {
        const int n = tid;
        const int pn = SW(n);
        float q = 0.0f;
#pragma unroll
        for (int k0 = 0; k0 < D; k0 += 8) {
            const int hk = (k0 >> 3) << 2;
            const float* col = &st[k0 * ST_STRIDE + (pn ^ hk)];
#pragma unroll
            for (int kk = 0; kk < 8; kk++) {
                float val = col[kk * ST_STRIDE];
                q = fmaf(val, val, q);
            }
        }
        qn_s[n] = q;
    }

    // ---- dot GEMM: dot[b][n] = <s_n, x_b>  (4b x 8n per thread) ----
    {
        const int w = tid >> 5;          // warp id = b-group
        const int lane = tid & 31;       // n-group
        const int b0 = 4 * w;
        const int pnA = SW(8 * lane);    // second quad is pnA ^ 4

        float dot[4][8];
#pragma unroll
        for (int a = 0; a < 4; a++)
#pragma unroll
            for (int j = 0; j < 8; j++) dot[a][j] = 0.0f;

#pragma unroll 1
        for (int k0 = 0; k0 < D; k0 += 8) {
            const int hk = (k0 >> 3) << 2;
            const int pA = pnA ^ hk;
#pragma unroll
            for (int kk = 0; kk < 8; kk++) {
                const int k = k0 + kk;
                const float4 xv = *(const float4*)&xs[k * XS_STRIDE + b0];
                const float4 s0 = *(const float4*)&st[k * ST_STRIDE + pA];
                const float4 s1 = *(const float4*)&st[k * ST_STRIDE + (pA ^ 4)];
                const float sv[8] = {s0.x, s0.y, s0.z, s0.w, s1.x, s1.y, s1.z, s1.w};
#pragma unroll
                for (int j = 0; j < 8; j++) {
                    dot[0][j] = fmaf(sv[j], xv.x, dot[0][j]);
                    dot[1][j] = fmaf(sv[j], xv.y, dot[1][j]);
                    dot[2][j] = fmaf(sv[j], xv.z, dot[2][j]);
                    dot[3][j] = fmaf(sv[j], xv.w, dot[3][j]);
                }
            }
        }
#pragma unroll
        for (int a = 0; a < 4; a++) {
            *(float4*)&G[(b0 + a) * G_STRIDE + pnA] =
                make_float4(dot[a][0], dot[a][1], dot[a][2], dot[a][3]);
            *(float4*)&G[(b0 + a) * G_STRIDE + (pnA ^ 4)] =
                make_float4(dot[a][4], dot[a][5], dot[a][6], dot[a][7]);
        }
    }
    __syncthreads();

    // ---- finalize: logits = c*(2*dot - q), tile softmax, weights back to G ----
    {
        const int row = tid >> 3;        // b
        const int sub = tid & 7;
        const float c = cb_s[row];
        float gv[32];
#pragma unroll
        for (int j = 0; j < 8; j++) {
            const int n = 4 * sub + 32 * j;
            const int pc = SW(n);
            const float4 dv = *(const float4*)&G[row * G_STRIDE + pc];
            const float4 qq = *(const float4*)&qn_s[n];
            gv[4 * j + 0] = c * (2.0f * dv.x - qq.x);
            gv[4 * j + 1] = c * (2.0f * dv.y - qq.y);
            gv[4 * j + 2] = c * (2.0f * dv.z - qq.z);
            gv[4 * j + 3] = c * (2.0f * dv.w - qq.w);
        }
        float m = gv[0];
#pragma unroll
        for (int i = 1; i < 32; i++) m = fmaxf(m, gv[i]);
        m = fmaxf(m, __shfl_xor_sync(0xffffffffu, m, 1));
        m = fmaxf(m, __shfl_xor_sync(0xffffffffu, m, 2));
        m = fmaxf(m, __shfl_xor_sync(0xffffffffu, m, 4));
        float l = 0.0f;
#pragma unroll
        for (int i = 0; i < 32; i++) {
            float p = __expf(gv[i] - m);
            gv[i] = p;
            l += p;
        }
#pragma unroll
        for (int j = 0; j < 8; j++) {
            const int n = 4 * sub + 32 * j;
            const int pc = SW(n);
            *(float4*)&G[row * G_STRIDE + pc] =
                make_float4(gv[4 * j], gv[4 * j + 1], gv[4 * j + 2], gv[4 * j + 3]);
        }
        l += __shfl_xor_sync(0xffffffffu, l, 1);
        l += __shfl_xor_sync(0xffffffffu, l, 2);
        l += __shfl_xor_sync(0xffffffffu, l, 4);
        if (sub == 0) { m_s[row] = m; l_s[row] = l; }
    }
    __syncthreads();

    // ---- acc GEMM: acc[b][d] = sum_n p[b][n]*s[n][d]  (4b x 8d, n split 4-way) ----
    const int qg   = tid >> 6;         // n quarter
    const int cell = tid & 63;
    const int dg   = cell & 7;         // d octet (lanes 0..7 span dg 0..7 -> conflict-free)
    const int bg2  = cell >> 3;        // b quad (broadcast within 8-lane phase)
    const int b0a  = 4 * bg2;
    const int d0   = 8 * dg;
    const int hd   = dg << 2;

    float acc[4][8];
#pragma unroll
    for (int a = 0; a < 4; a++)
#pragma unroll
        for (int r = 0; r < 8; r++) acc[a][r] = 0.0f;

    {
        const int nbase = 64 * qg;
#pragma unroll 2
        for (int n4 = 0; n4 < 64; n4 += 4) {
            const int n = nbase + n4;
            const int pg = SW(n);
            const int ps = pg ^ hd;
            const float4 p0 = *(const float4*)&G[(b0a + 0) * G_STRIDE + pg];
            const float4 p1 = *(const float4*)&G[(b0a + 1) * G_STRIDE + pg];
            const float4 p2 = *(const float4*)&G[(b0a + 2) * G_STRIDE + pg];
            const float4 p3 = *(const float4*)&G[(b0a + 3) * G_STRIDE + pg];
#pragma unroll
            for (int r = 0; r < 8; r++) {
                const float4 sv = *(const float4*)&st[(d0 + r) * ST_STRIDE + ps];
                acc[0][r] = fmaf(p0.x, sv.x, acc[0][r]);
                acc[0][r] = fmaf(p0.y, sv.y, acc[0][r]);
                acc[0][r] = fmaf(p0.z, sv.z, acc[0][r]);
                acc[0][r] = fmaf(p0.w, sv.w, acc[0][r]);
                acc[1][r] = fmaf(p1.x, sv.x, acc[1][r]);
                acc[1][r] = fmaf(p1.y, sv.y, acc[1][r]);
                acc[1][r] = fmaf(p1.z, sv.z, acc[1][r]);
                acc[1][r] = fmaf(p1.w, sv.w, acc[1][r]);
                acc[2][r] = fmaf(p2.x, sv.x, acc[2][r]);
                acc[2][r] = fmaf(p2.y, sv.y, acc[2][r]);
                acc[2][r] = fmaf(p2.z, sv.z, acc[2][r]);
                acc[2][r] = fmaf(p2.w, sv.w, acc[2][r]);
                acc[3][r] = fmaf(p3.x, sv.x, acc[3][r]);
                acc[3][r] = fmaf(p3.y, sv.y, acc[3][r]);
                acc[3][r] = fmaf(p3.z, sv.z, acc[3][r]);
                acc[3][r] = fmaf(p3.w, sv.w, acc[3][r]);
            }
        }
    }
    __syncthreads();            // done reading G; reuse it as combine buffer

    // ---- combine n-quarters and write partials ----
    float* buf = G;             // 4*64*32 = 8192 floats, exactly G's size
    {
        float* bp = &buf[(qg * 64 + cell) * 32];
#pragma unroll
        for (int a = 0; a < 4; a++) {
            *(float4*)&bp[a * 8 + 0] = make_float4(acc[a][0], acc[a][1], acc[a][2], acc[a][3]);
            *(float4*)&bp[a * 8 + 4] = make_float4(acc[a][4], acc[a][5], acc[a][6], acc[a][7]);
        }
    }
    __syncthreads();
    {
        const int a2 = tid >> 6;
        const int c2 = tid & 63;
        float4 sA = make_float4(0.f, 0.f, 0.f, 0.f);
        float4 sB = make_float4(0.f, 0.f, 0.f, 0.f);
#pragma unroll
        for (int q2 = 0; q2 < 4; q2++) {
            const float* bp = &buf[(q2 * 64 + c2) * 32 + a2 * 8];
            const float4 uA = *(const float4*)&bp[0];
            const float4 uB = *(const float4*)&bp[4];
            sA.x += uA.x; sA.y += uA.y; sA.z += uA.z; sA.w += uA.w;
            sB.x += uB.x; sB.y += uB.y; sB.z += uB.z; sB.w += uB.w;
        }
        const int bglob = 4 * (c2 >> 3) + a2;
        const int dbase = 8 * (c2 & 7);
        *(float4*)&g_acc[blockIdx.x][bglob][dbase + 0] = sA;
        *(float4*)&g_acc[blockIdx.x][bglob][dbase + 4] = sB;
    }
    if (tid < B) {
        g_m[blockIdx.x][tid] = m_s[tid];
        g_l[blockIdx.x][tid] = l_s[tid];
    }
}

__global__ __launch_bounds__(512)
void score_reduce_kernel(const float* __restrict__ t,
                         const float* __restrict__ x,
                         float* __restrict__ out) {
    const int b = blockIdx.x;
    const int tid = threadIdx.x;
    __shared__ float me[GRID_MAIN];
    __shared__ float e[GRID_MAIN];
    __shared__ float racc[8][D + 4];
    __shared__ float Ms, Ls;

    if (tid < GRID_MAIN) me[tid] = g_m[tid][b];
    __syncthreads();
    if (tid < 32) {
        float m = me[tid];
#pragma unroll
        for (int k = 1; k < 8; k++) m = fmaxf(m, me[tid + 32 * k]);
#pragma unroll
        for (int s = 16; s; s >>= 1) m = fmaxf(m, __shfl_xor_sync(0xffffffffu, m, s));
        if (tid == 0) Ms = m;
    }
    __syncthreads();
    const float M = Ms;
    if (tid < GRID_MAIN) e[tid] = __expf(me[tid] - M);   // exp ONCE per partial
    __syncthreads();
    if (tid < 32) {
        float l = 0.0f;
#pragma unroll
        for (int k = 0; k < 8; k++) {
            int i = tid + 32 * k;
            l = fmaf(e[i], g_l[i][b], l);
        }
#pragma unroll
        for (int s = 16; s; s >>= 1) l += __shfl_xor_sync(0xffffffffu, l, s);
        if (tid == 0) Ls = l;
    }
    // pure-FMA acc reduction (no MUFU in the hot loop)
    const int ig = tid >> 6;   // 0..7
    const int d  = tid & 63;
    float a = 0.0f;
#pragma unroll 8
    for (int i = ig; i < GRID_MAIN; i += 8)
        a = fmaf(e[i], g_acc[i][b][d], a);
    racc[ig][d] = a;
    __syncthreads();
    if (tid < D) {
        float A = 0.0f;
#pragma unroll
        for (int k = 0; k < 8; k++) A += racc[k][tid];
        float sig = 0.01f * expf(t[b] * 9.210340371976184f);
        out[b * D + tid] = (1.0f / sig) * (A / Ls - x[b * D + tid]);
    }
}

extern "C" void kernel_launch(void* const* d_in, const int* in_sizes, int n_in,
                              void* d_out, int out_size) {
    const float* t = nullptr;
    const float* x = nullptr;
    const float* s = nullptr;
    for (int i = 0; i < n_in; i++) {
        if      (in_sizes[i] == B)      t = (const float*)d_in[i];
        else if (in_sizes[i] == B * D)  x = (const float*)d_in[i];
        else if (in_sizes[i] == NS * D) s = (const float*)d_in[i];
    }
    cudaFuncSetAttribute(score_partial_kernel,
                         cudaFuncAttributeMaxDynamicSharedMemorySize, SMEM_BYTES);
    score_partial_kernel<<<GRID_MAIN, THREADS, SMEM_BYTES>>>(t, x, s);
    score_reduce_kernel<<<B, 512>>>(t, x, (float*)d_out);
}

// round 4
// speedup vs baseline: 1.3947x; 1.0399x over previous
// SampleScoreModel: softmax-weighted Gaussian-kernel score (flash-attention style).
// Round 4 = round 3 resubmitted (container infra failure, kernel never ran):
// packed fma.rn.f32x2 in both GEMMs (halves FMA-pipe warp-instrs),
// softmax fused into dist-GEMM registers, MLP-optimized reduce kernel.
#include <cuda_runtime.h>
#include <math.h>
#include <float.h>

#define B 32
#define D 64
#define NS 65536
#define TILE 256
#define GRID_MAIN (NS / TILE)   // 256
#define THREADS 256

#define ST_STRIDE 256
#define G_STRIDE 256
#define XS_STRIDE 36

// base column swizzle (bits2..4 ^= bits3..5); bijective per 32-block, keeps 4-float granules
#define SW(n) ((n) ^ ((((n) >> 3) & 7) << 2))

// smem layout (floats)
#define OFF_ST 0                         // 64*256 = 16384
#define OFF_G  16384                     // 32*256 = 8192
#define OFF_XS 24576                     // 64*36  = 2304
#define OFF_Q  26880                     // 256
#define OFF_CB 27136                     // 32
#define OFF_M  27168                     // 32
#define OFF_L  27200                     // 32
#define SMEM_FLOATS 27232
#define SMEM_BYTES (SMEM_FLOATS * 4)     // 108,928 B -> 2 CTAs/SM

// packed f32x2 FMA: both 32-bit halves do independent fp32 fma
#define FMA2(acc, a, b) \
    asm("fma.rn.f32x2 %0, %1, %2, %0;" : "+l"(acc) : "l"(a), "l"(b))
#define DUP2(d, f) \
    asm("mov.b64 %0, {%1, %1};" : "=l"(d) : "r"(__float_as_uint(f)))

__device__ __forceinline__ float lo32(unsigned long long u) {
    return __uint_as_float((unsigned)u);
}
__device__ __forceinline__ float hi32(unsigned long long u) {
    return __uint_as_float((unsigned)(u >> 32));
}

__device__ float g_acc[GRID_MAIN][B][D];
__device__ float g_m[GRID_MAIN][B];
__device__ float g_l[GRID_MAIN][B];

__global__ __launch_bounds__(THREADS, 2)
void score_partial_kernel(const float* __restrict__ t,
                          const float* __restrict__ x,
                          const float* __restrict__ samples) {
    extern __shared__ float sm[];
    float* st   = sm + OFF_ST;   // sample tile [d][pcol], pcol = SW(n) ^ (((d>>3)&7)<<2)
    float* G    = sm + OFF_G;    // softmax weights, [b][SW(n)]
    float* xs   = sm + OFF_XS;   // x transposed [k][b]
    float* qn_s = sm + OFF_Q;    // ||s_n||^2 at [SW(n)]
    float* cb_s = sm + OFF_CB;   // 0.5 / sigma^2 per b
    float* m_s  = sm + OFF_M;
    float* l_s  = sm + OFF_L;

    const int tid = threadIdx.x;

    // ---- setup: x transpose + per-b constants ----
#pragma unroll
    for (int i = tid; i < B * D; i += THREADS) {
        int b = i >> 6, k = i & 63;
        xs[k * XS_STRIDE + b] = x[i];
    }
    if (tid < B) {
        float sig = 0.01f * expf(t[tid] * 9.210340371976184f); // smin*(smax/smin)^t
        cb_s[tid] = 0.5f / (sig * sig);
    }

    // ---- coalesced global load: flat float4 index = tid + 256*j ----
    const int nn2 = tid >> 4;     // row within 16-group
    const int d4  = tid & 15;     // float4 column
    const float4* sp = (const float4*)samples;
    const size_t base = (size_t)blockIdx.x * (TILE * (D / 4));
    float4 v[16];
#pragma unroll
    for (int j = 0; j < 16; j++) v[j] = sp[base + tid + 256 * j];

    // ---- transpose-store into st with d-dependent swizzle ----
    const int h4st = (d4 >> 1) << 2;      // ((d>>3)&7)<<2 for rows 4*d4..4*d4+3
#pragma unroll
    for (int j = 0; j < 16; j++) {
        int n = 16 * j + nn2;
        int pc = SW(n) ^ h4st;
        float* p = &st[(4 * d4) * ST_STRIDE + pc];
        p[0 * ST_STRIDE] = v[j].x;
        p[1 * ST_STRIDE] = v[j].y;
        p[2 * ST_STRIDE] = v[j].z;
        p[3 * ST_STRIDE] = v[j].w;
    }
    __syncthreads();

    // ---- q_n = ||s_n||^2 (column pass, one n per thread), stored at SW(n) ----
    {
        const int n = tid;
        const int pn = SW(n);
        float q = 0.0f;
#pragma unroll
        for (int k0 = 0; k0 < D; k0 += 8) {
            const int hk = (k0 >> 3) << 2;
            const float* col = &st[k0 * ST_STRIDE + (pn ^ hk)];
#pragma unroll
            for (int kk = 0; kk < 8; kk++) {
                float val = col[kk * ST_STRIDE];
                q = fmaf(val, val, q);
            }
        }
        qn_s[pn] = q;
    }
    __syncthreads();   // q visible to all before finalize reads

    // ---- dot GEMM (f32x2, n-paired): dot[b][n] = <s_n, x_b>, 4b x 8n/thread ----
    // then softmax fused in registers: each warp owns b0..b0+3 over all 256 n.
    {
        const int w    = tid >> 5;
        const int lane = tid & 31;
        const int b0   = 4 * w;
        const int pnA  = SW(8 * lane);

        unsigned long long dot2[4][4];
#pragma unroll
        for (int a = 0; a < 4; a++)
#pragma unroll
            for (int jp = 0; jp < 4; jp++) dot2[a][jp] = 0ull;

#pragma unroll 1
        for (int k0 = 0; k0 < D; k0 += 8) {
            const int hk = (k0 >> 3) << 2;
            const int pA = pnA ^ hk;
#pragma unroll
            for (int kk = 0; kk < 8; kk++) {
                const int k = k0 + kk;
                const float4 xv = *(const float4*)&xs[k * XS_STRIDE + b0];
                unsigned long long xd0, xd1, xd2, xd3;
                DUP2(xd0, xv.x); DUP2(xd1, xv.y); DUP2(xd2, xv.z); DUP2(xd3, xv.w);
                const ulonglong2 s01 = *(const ulonglong2*)&st[k * ST_STRIDE + pA];
                const ulonglong2 s23 = *(const ulonglong2*)&st[k * ST_STRIDE + (pA ^ 4)];
                FMA2(dot2[0][0], xd0, s01.x); FMA2(dot2[0][1], xd0, s01.y);
                FMA2(dot2[0][2], xd0, s23.x); FMA2(dot2[0][3], xd0, s23.y);
                FMA2(dot2[1][0], xd1, s01.x); FMA2(dot2[1][1], xd1, s01.y);
                FMA2(dot2[1][2], xd1, s23.x); FMA2(dot2[1][3], xd1, s23.y);
                FMA2(dot2[2][0], xd2, s01.x); FMA2(dot2[2][1], xd2, s01.y);
                FMA2(dot2[2][2], xd2, s23.x); FMA2(dot2[2][3], xd2, s23.y);
                FMA2(dot2[3][0], xd3, s01.x); FMA2(dot2[3][1], xd3, s01.y);
                FMA2(dot2[3][2], xd3, s23.x); FMA2(dot2[3][3], xd3, s23.y);
            }
        }

        // q for this thread's 8 n's (quads at pnA, pnA^4)
        const float4 q0 = *(const float4*)&qn_s[pnA];
        const float4 q1 = *(const float4*)&qn_s[pnA ^ 4];
        const float qv[8] = {q0.x, q0.y, q0.z, q0.w, q1.x, q1.y, q1.z, q1.w};

#pragma unroll
        for (int a = 0; a < 4; a++) {
            const float c = cb_s[b0 + a];
            float gv[8];
#pragma unroll
            for (int jp = 0; jp < 4; jp++) {
                gv[2 * jp    ] = c * (2.0f * lo32(dot2[a][jp]) - qv[2 * jp]);
                gv[2 * jp + 1] = c * (2.0f * hi32(dot2[a][jp]) - qv[2 * jp + 1]);
            }
            float m = gv[0];
#pragma unroll
            for (int i = 1; i < 8; i++) m = fmaxf(m, gv[i]);
#pragma unroll
            for (int s = 16; s; s >>= 1) m = fmaxf(m, __shfl_xor_sync(0xffffffffu, m, s));
            float l = 0.0f;
#pragma unroll
            for (int i = 0; i < 8; i++) {
                float p = __expf(gv[i] - m);
                gv[i] = p;
                l += p;
            }
            *(float4*)&G[(b0 + a) * G_STRIDE + pnA] =
                make_float4(gv[0], gv[1], gv[2], gv[3]);
            *(float4*)&G[(b0 + a) * G_STRIDE + (pnA ^ 4)] =
                make_float4(gv[4], gv[5], gv[6], gv[7]);
#pragma unroll
            for (int s = 16; s; s >>= 1) l += __shfl_xor_sync(0xffffffffu, l, s);
            if (lane == 0) { m_s[b0 + a] = m; l_s[b0 + a] = l; }
        }
    }
    __syncthreads();

    // ---- acc GEMM (f32x2, n-paired dual accumulators): acc[b][d] += p*s ----
    const int qg   = tid >> 6;         // n quarter
    const int cell = tid & 63;
    const int dg   = cell & 7;         // d octet
    const int bg2  = cell >> 3;        // b quad
    const int b0a  = 4 * bg2;
    const int d0   = 8 * dg;
    const int hd   = dg << 2;

    unsigned long long acc2[4][8];
#pragma unroll
    for (int a = 0; a < 4; a++)
#pragma unroll
        for (int r = 0; r < 8; r++) acc2[a][r] = 0ull;

    {
        const int nbase = 64 * qg;
#pragma unroll 2
        for (int n4 = 0; n4 < 64; n4 += 4) {
            const int n = nbase + n4;
            const int pg = SW(n);
            const int ps = pg ^ hd;
            const ulonglong2 p0 = *(const ulonglong2*)&G[(b0a + 0) * G_STRIDE + pg];
            const ulonglong2 p1 = *(const ulonglong2*)&G[(b0a + 1) * G_STRIDE + pg];
            const ulonglong2 p2 = *(const ulonglong2*)&G[(b0a + 2) * G_STRIDE + pg];
            const ulonglong2 p3 = *(const ulonglong2*)&G[(b0a + 3) * G_STRIDE + pg];
#pragma unroll
            for (int r = 0; r < 8; r++) {
                const ulonglong2 sv = *(const ulonglong2*)&st[(d0 + r) * ST_STRIDE + ps];
                FMA2(acc2[0][r], p0.x, sv.x); FMA2(acc2[0][r], p0.y, sv.y);
                FMA2(acc2[1][r], p1.x, sv.x); FMA2(acc2[1][r], p1.y, sv.y);
                FMA2(acc2[2][r], p2.x, sv.x); FMA2(acc2[2][r], p2.y, sv.y);
                FMA2(acc2[3][r], p3.x, sv.x); FMA2(acc2[3][r], p3.y, sv.y);
            }
        }
    }

    float acc[4][8];
#pragma unroll
    for (int a = 0; a < 4; a++)
#pragma unroll
        for (int r = 0; r < 8; r++)
            acc[a][r] = lo32(acc2[a][r]) + hi32(acc2[a][r]);

    __syncthreads();            // done reading G; reuse it as combine buffer

    // ---- combine n-quarters and write partials ----
    float* buf = G;             // 4*64*32 = 8192 floats, exactly G's size
    {
        float* bp = &buf[(qg * 64 + cell) * 32];
#pragma unroll
        for (int a = 0; a < 4; a++) {
            *(float4*)&bp[a * 8 + 0] = make_float4(acc[a][0], acc[a][1], acc[a][2], acc[a][3]);
            *(float4*)&bp[a * 8 + 4] = make_float4(acc[a][4], acc[a][5], acc[a][6], acc[a][7]);
        }
    }
    __syncthreads();
    {
        const int a2 = tid >> 6;
        const int c2 = tid & 63;
        float4 sA = make_float4(0.f, 0.f, 0.f, 0.f);
        float4 sB = make_float4(0.f, 0.f, 0.f, 0.f);
#pragma unroll
        for (int q2 = 0; q2 < 4; q2++) {
            const float* bp = &buf[(q2 * 64 + c2) * 32 + a2 * 8];
            const float4 uA = *(const float4*)&bp[0];
            const float4 uB = *(const float4*)&bp[4];
            sA.x += uA.x; sA.y += uA.y; sA.z += uA.z; sA.w += uA.w;
            sB.x += uB.x; sB.y += uB.y; sB.z += uB.z; sB.w += uB.w;
        }
        const int bglob = 4 * (c2 >> 3) + a2;
        const int dbase = 8 * (c2 & 7);
        *(float4*)&g_acc[blockIdx.x][bglob][dbase + 0] = sA;
        *(float4*)&g_acc[blockIdx.x][bglob][dbase + 4] = sB;
    }
    if (tid < B) {
        g_m[blockIdx.x][tid] = m_s[tid];
        g_l[blockIdx.x][tid] = l_s[tid];
    }
}

__global__ __launch_bounds__(512)
void score_reduce_kernel(const float* __restrict__ t,
                         const float* __restrict__ x,
                         float* __restrict__ out) {
    const int b = blockIdx.x;
    const int tid = threadIdx.x;
    __shared__ float me[GRID_MAIN];
    __shared__ float e[GRID_MAIN];
    __shared__ float racc[32][68];
    __shared__ float Ms, Ls;

    if (tid < GRID_MAIN) me[tid] = g_m[tid][b];
    __syncthreads();
    if (tid < 32) {
        float m = me[tid];
#pragma unroll
        for (int k = 1; k < 8; k++) m = fmaxf(m, me[tid + 32 * k]);
#pragma unroll
        for (int s = 16; s; s >>= 1) m = fmaxf(m, __shfl_xor_sync(0xffffffffu, m, s));
        if (tid == 0) Ms = m;
    }
    __syncthreads();
    if (tid < GRID_MAIN) e[tid] = __expf(me[tid] - Ms);   // exp ONCE per partial
    __syncthreads();
    if (tid < 32) {
        float l = 0.0f;
#pragma unroll
        for (int k = 0; k < 8; k++) {
            int i = tid + 32 * k;
            l = fmaf(e[i], g_l[i][b], l);
        }
#pragma unroll
        for (int s = 16; s; s >>= 1) l += __shfl_xor_sync(0xffffffffu, l, s);
        if (tid == 0) Ls = l;
    }
    // vectorized, MLP-deep acc reduction: 32 i-groups x 16 float4-columns
    const int ig = tid >> 4;   // 0..31
    const int dd = tid & 15;   // float4 column
    float4 a4 = make_float4(0.f, 0.f, 0.f, 0.f);
#pragma unroll
    for (int k = 0; k < 8; k++) {
        const int i = ig + 32 * k;
        const float4 v = *(const float4*)&g_acc[i][b][4 * dd];
        const float ei = e[i];
        a4.x = fmaf(ei, v.x, a4.x);
        a4.y = fmaf(ei, v.y, a4.y);
        a4.z = fmaf(ei, v.z, a4.z);
        a4.w = fmaf(ei, v.w, a4.w);
    }
    *(float4*)&racc[ig][4 * dd] = a4;
    __syncthreads();
    if (tid < D) {
        float A = 0.0f;
#pragma unroll
        for (int g2 = 0; g2 < 32; g2++) A += racc[g2][tid];
        float sig = 0.01f * expf(t[b] * 9.210340371976184f);
        out[b * D + tid] = (1.0f / sig) * (A / Ls - x[b * D + tid]);
    }
}

extern "C" void kernel_launch(void* const* d_in, const int* in_sizes, int n_in,
                              void* d_out, int out_size) {
    const float* t = nullptr;
    const float* x = nullptr;
    const float* s = nullptr;
    for (int i = 0; i < n_in; i++) {
        if      (in_sizes[i] == B)      t = (const float*)d_in[i];
        else if (in_sizes[i] == B * D)  x = (const float*)d_in[i];
        else if (in_sizes[i] == NS * D) s = (const float*)d_in[i];
    }
    cudaFuncSetAttribute(score_partial_kernel,
                         cudaFuncAttributeMaxDynamicSharedMemorySize, SMEM_BYTES);
    score_partial_kernel<<<GRID_MAIN, THREADS, SMEM_BYTES>>>(t, x, s);
    score_reduce_kernel<<<B, 512>>>(t, x, (float*)d_out);
}